// round 12
// baseline (speedup 1.0000x reference)
#include <cuda_runtime.h>
#include <cstdint>

#define BATCH 512
#define CHAN  1024
#define HW    64
#define EPS_F 1e-8f
#define TINY_F 1.17549435e-38f
#define SLICES 4
#define CPS    (CHAN / SLICES)
#define MAXBLK (BATCH * SLICES)   // 2048
#define GUMBLK 128                // 128*256 = 32768 gumbels
#define APPBLK 4096               // 4096 blocks * 2048 float4 = whole tensor

// scratch
__device__ float g_part[BATCH * SLICES * HW];
__device__ float g_gumbel[BATCH * HW];

// ---------------------------------------------------------------------------
// Threefry-2x32-20 (JAX), key = (0,1)
// ---------------------------------------------------------------------------
__device__ __forceinline__ unsigned rotl32(unsigned x, int r) {
    return (x << r) | (x >> (32 - r));
}

__device__ __forceinline__ unsigned threefry_out(unsigned idx) {
    const unsigned half = 16384u;
    unsigned c0, c1;
    bool first = (idx < half);
    if (first) { c0 = idx; c1 = idx + half; }
    else       { c0 = idx - half; c1 = idx; }

    const unsigned ks0 = 0u, ks1 = 1u, ks2 = 0x1BD11BDBu;
    unsigned ksv[3] = {ks0, ks1, ks2};
    const int rotA[4] = {13, 15, 26, 6};
    const int rotB[4] = {17, 29, 16, 24};

    unsigned x0 = c0 + ks0;
    unsigned x1 = c1 + ks1;

#pragma unroll
    for (int i = 0; i < 5; i++) {
#pragma unroll
        for (int j = 0; j < 4; j++) {
            int r = ((i & 1) == 0) ? rotA[j] : rotB[j];
            x0 += x1;
            x1 = rotl32(x1, r);
            x1 ^= x0;
        }
        x0 += ksv[(i + 1) % 3];
        x1 += ksv[(i + 2) % 3] + (unsigned)(i + 1);
    }
    return first ? x0 : x1;
}

__device__ __forceinline__ float gumbel_at(unsigned idx) {
    unsigned bits = threefry_out(idx);
    float f = __uint_as_float((bits >> 9) | 0x3f800000u) - 1.0f;
    float u = fmaxf(TINY_F, f + TINY_F);
    double lg = -log(-log((double)u));
    return (float)lg;
}

// ---------------------------------------------------------------------------
// L1: max role (R7 K1a verbatim) + gumbel-table role.
// ---------------------------------------------------------------------------
__global__ __launch_bounds__(256) void max_kernel(const float* __restrict__ x)
{
    const int t = threadIdx.x;
    const int bi = blockIdx.x;

    if (bi < MAXBLK) {
        __shared__ float4 red[256];
        const float4* __restrict__ xp = (const float4*)x + (size_t)bi * (CPS * HW / 4);

        float4 acc = make_float4(-3.4e38f, -3.4e38f, -3.4e38f, -3.4e38f);
#pragma unroll
        for (int i = 0; i < 16; i++) {
            float4 val = xp[i * 256 + t];
            acc.x = fmaxf(acc.x, val.x);
            acc.y = fmaxf(acc.y, val.y);
            acc.z = fmaxf(acc.z, val.z);
            acc.w = fmaxf(acc.w, val.w);
        }
        red[t] = acc;
        __syncthreads();

        if (t < 16) {
            float4 m4 = red[t];
#pragma unroll
            for (int g = 1; g < 16; g++) {
                float4 o = red[g * 16 + t];
                m4.x = fmaxf(m4.x, o.x);
                m4.y = fmaxf(m4.y, o.y);
                m4.z = fmaxf(m4.z, o.z);
                m4.w = fmaxf(m4.w, o.w);
            }
            ((float4*)(g_part + (size_t)bi * HW))[t] = m4;
        }
        return;
    }

    // gumbel-table role
    {
        const int g = bi - MAXBLK;
        unsigned idx = (unsigned)g * 256u + (unsigned)t;
        g_gumbel[idx] = gumbel_at(idx);
    }
}

// ---------------------------------------------------------------------------
// L2: apply kernel. Per-block redundant gate (low-reg prologue), then the
// R7-proven stream: reverse block order, plain cached loads (MLP=8), __stcs.
// ---------------------------------------------------------------------------
__global__ __launch_bounds__(256) void apply_kernel(
    const float4* __restrict__ x4,
    float4* __restrict__ out4,
    const float* __restrict__ w1_1,
    const float* __restrict__ w5,
    const float* __restrict__ b5,
    const float* __restrict__ w6,
    const float* __restrict__ b6)
{
    __shared__ float m[64], pre[16], c1[16], up[64], hid[4][64], gs[64];
    __shared__ float w1s[9], w5s[72], b5s[4], w6s[36], b6s;

    const int t = threadIdx.x;
    const int blk = gridDim.x - 1 - blockIdx.x;          // reverse order
    const size_t base = (size_t)blk * 2048 + t;
    const int b = (int)(base >> 14);                     // batch, block-constant

    // ---- gate prologue (no x data live; ~38 regs total) ----
    if (t < 9)  w1s[t] = w1_1[t];
    if (t < 72) w5s[t] = w5[t];
    if (t < 4)  b5s[t] = b5[t];
    if (t < 36) w6s[t] = w6[t];
    if (t == 0) b6s = b6[0];

    if (t < 64) {
        float mv = g_part[(size_t)(b * SLICES) * HW + t];
#pragma unroll
        for (int s2 = 1; s2 < SLICES; s2++)
            mv = fmaxf(mv, g_part[(size_t)(b * SLICES + s2) * HW + t]);
        m[t] = mv;
    }
    __syncthreads();

    if (t < 16) {
        int wh = t >> 2, ww = t & 3;
        float w0  = m[(2 * wh) * 8 + 2 * ww];
        float w1v = m[(2 * wh) * 8 + 2 * ww + 1];
        float w2  = m[(2 * wh + 1) * 8 + 2 * ww];
        float w3  = m[(2 * wh + 1) * 8 + 2 * ww + 1];
        float wraw[4] = {w0, w1v, w2, w3};
        float wc[4];
#pragma unroll
        for (int k = 0; k < 4; k++) {
            float val = wraw[k];
            wc[k] = (!isfinite(val) || val < 0.0f) ? EPS_F : val;
        }
        const float* gt = g_gumbel + (size_t)b * 64 + t * 4;
        int best = 0;
        float bestv = wc[0] + gt[0];
#pragma unroll
        for (int k = 1; k < 4; k++) {
            float cand = wc[k] + gt[k];
            if (cand > bestv) { bestv = cand; best = k; }
        }
        float mo2 = wc[best];
        float mo3 = fmaxf(fmaxf(w0, w1v), fmaxf(w2, w3));
        float ao4 = (w0 + w1v + w2 + w3) * 0.25f;
        pre[t] = 0.1f * mo2 + 0.6f * mo3 + 0.3f * ao4;
    }
    __syncthreads();

    if (t < 16) {
        int i = t >> 2, j = t & 3;
        float acc1 = 0.0f;
#pragma unroll
        for (int di = 0; di < 3; di++) {
            int ii = i + di - 1;
            if (ii < 0 || ii >= 4) continue;
#pragma unroll
            for (int dj = 0; dj < 3; dj++) {
                int jj = j + dj - 1;
                if (jj < 0 || jj >= 4) continue;
                acc1 += pre[ii * 4 + jj] * w1s[di * 3 + dj];
            }
        }
        c1[t] = acc1;
    }
    __syncthreads();

    if (t < 64) {
        const int j0t[8] = {0, 0, 0, 1, 1, 2, 2, 3};
        const int j1t[8] = {0, 1, 1, 2, 2, 3, 3, 3};
        const float wt[8] = {1.0f, 0.75f, 0.25f, 0.75f, 0.25f, 0.75f, 0.25f, 1.0f};
        int y = t >> 3, xo = t & 7;
        float wy = wt[y], wx = wt[xo];
        float r0 = wx * c1[j0t[y] * 4 + j0t[xo]] + (1.0f - wx) * c1[j0t[y] * 4 + j1t[xo]];
        float r1 = wx * c1[j1t[y] * 4 + j0t[xo]] + (1.0f - wx) * c1[j1t[y] * 4 + j1t[xo]];
        up[t] = wy * r0 + (1.0f - wy) * r1;
    }
    __syncthreads();

    if (t < 64) {
        int y = t >> 3, xo = t & 7;
#pragma unroll
        for (int oc = 0; oc < 4; oc++) {
            float acc5 = b5s[oc];
#pragma unroll
            for (int di = 0; di < 3; di++) {
                int yy = y + di - 1;
                if (yy < 0 || yy >= 8) continue;
#pragma unroll
                for (int dj = 0; dj < 3; dj++) {
                    int xx = xo + dj - 1;
                    if (xx < 0 || xx >= 8) continue;
                    int pix = yy * 8 + xx;
                    acc5 += m[pix]  * w5s[oc * 18 + 0 * 9 + di * 3 + dj];
                    acc5 += up[pix] * w5s[oc * 18 + 1 * 9 + di * 3 + dj];
                }
            }
            hid[oc][t] = fmaxf(acc5, 0.0f);
        }
    }
    __syncthreads();

    if (t < 64) {
        int y = t >> 3, xo = t & 7;
        float acc6 = b6s;
#pragma unroll
        for (int oc = 0; oc < 4; oc++) {
#pragma unroll
            for (int di = 0; di < 3; di++) {
                int yy = y + di - 1;
                if (yy < 0 || yy >= 8) continue;
#pragma unroll
                for (int dj = 0; dj < 3; dj++) {
                    int xx = xo + dj - 1;
                    if (xx < 0 || xx >= 8) continue;
                    acc6 += hid[oc][yy * 8 + xx] * w6s[oc * 9 + di * 3 + dj];
                }
            }
        }
        gs[t] = 1.0f / (1.0f + expf(-acc6));
    }
    __syncthreads();

    // ---- R7-proven stream: 8 front-batched cached loads, __stcs stores ----
    const float4 gv = ((const float4*)gs)[t & 15];
    float4 xv[8];
#pragma unroll
    for (int k = 0; k < 8; k++)
        xv[k] = x4[base + k * 256];

#pragma unroll
    for (int k = 0; k < 8; k++) {
        float4 o;
        o.x = fmaxf(xv[k].x * gv.x, 0.0f);
        o.y = fmaxf(xv[k].y * gv.y, 0.0f);
        o.z = fmaxf(xv[k].z * gv.z, 0.0f);
        o.w = fmaxf(xv[k].w * gv.w, 0.0f);
        __stcs(&out4[base + k * 256], o);
    }
}

extern "C" void kernel_launch(void* const* d_in, const int* in_sizes, int n_in,
                              void* d_out, int out_size)
{
    const float* x    = (const float*)d_in[0];
    const float* w1_1 = (const float*)d_in[1];
    const float* w5   = (const float*)d_in[2];
    const float* b5   = (const float*)d_in[3];
    const float* w6   = (const float*)d_in[4];
    const float* b6   = (const float*)d_in[5];
    const float4* x4  = (const float4*)x;
    float4* out4 = (float4*)d_out;

    max_kernel<<<MAXBLK + GUMBLK, 256>>>(x);
    apply_kernel<<<APPBLK, 256>>>(x4, out4, w1_1, w5, b5, w6, b6);
}

// round 14
// speedup vs baseline: 1.0519x; 1.0519x over previous
#include <cuda_runtime.h>
#include <cstdint>

#define BATCH 512
#define CHAN  1024
#define HW    64
#define EPS_F 1e-8f
#define TINY_F 1.17549435e-38f
#define SLICES 4
#define CPS   (CHAN / SLICES)

// scratch
__device__ float g_part[BATCH * SLICES * HW];
__device__ float g_gate[BATCH * HW];

// ---------------------------------------------------------------------------
// Threefry-2x32-20 (JAX), key = (0,1)
// ---------------------------------------------------------------------------
__device__ __forceinline__ unsigned rotl32(unsigned x, int r) {
    return (x << r) | (x >> (32 - r));
}

__device__ __forceinline__ unsigned threefry_out(unsigned idx) {
    const unsigned half = 16384u;
    unsigned c0, c1;
    bool first = (idx < half);
    if (first) { c0 = idx; c1 = idx + half; }
    else       { c0 = idx - half; c1 = idx; }

    const unsigned ks0 = 0u, ks1 = 1u, ks2 = 0x1BD11BDBu;
    unsigned ksv[3] = {ks0, ks1, ks2};
    const int rotA[4] = {13, 15, 26, 6};
    const int rotB[4] = {17, 29, 16, 24};

    unsigned x0 = c0 + ks0;
    unsigned x1 = c1 + ks1;

#pragma unroll
    for (int i = 0; i < 5; i++) {
#pragma unroll
        for (int j = 0; j < 4; j++) {
            int r = ((i & 1) == 0) ? rotA[j] : rotB[j];
            x0 += x1;
            x1 = rotl32(x1, r);
            x1 ^= x0;
        }
        x0 += ksv[(i + 1) % 3];
        x1 += ksv[(i + 2) % 3] + (unsigned)(i + 1);
    }
    return first ? x0 : x1;
}

__device__ __forceinline__ float gumbel_at(unsigned idx) {
    unsigned bits = threefry_out(idx);
    float f = __uint_as_float((bits >> 9) | 0x3f800000u) - 1.0f;
    float u = fmaxf(TINY_F, f + TINY_F);
    double lg = -log(-log((double)u));
    return (float)lg;
}

// ---------------------------------------------------------------------------
// K1a: partial channel max. grid = BATCH*SLICES, 256 threads. (R7 verbatim)
// ---------------------------------------------------------------------------
__global__ __launch_bounds__(256) void partial_max_kernel(const float* __restrict__ x)
{
    __shared__ float4 red[256];
    const int t = threadIdx.x;
    const int bid = blockIdx.x;

    const float4* __restrict__ xp = (const float4*)x + (size_t)bid * (CPS * HW / 4);

    float4 acc = make_float4(-3.4e38f, -3.4e38f, -3.4e38f, -3.4e38f);
#pragma unroll
    for (int i = 0; i < 16; i++) {
        float4 val = xp[i * 256 + t];
        acc.x = fmaxf(acc.x, val.x);
        acc.y = fmaxf(acc.y, val.y);
        acc.z = fmaxf(acc.z, val.z);
        acc.w = fmaxf(acc.w, val.w);
    }
    red[t] = acc;
    __syncthreads();

    if (t < 16) {
        float4 m4 = red[t];
#pragma unroll
        for (int g = 1; g < 16; g++) {
            float4 o = red[g * 16 + t];
            m4.x = fmaxf(m4.x, o.x);
            m4.y = fmaxf(m4.y, o.y);
            m4.z = fmaxf(m4.z, o.z);
            m4.w = fmaxf(m4.w, o.w);
        }
        ((float4*)(g_part + (size_t)bid * HW))[t] = m4;
    }
}

// ---------------------------------------------------------------------------
// K1b: gate pipeline. grid = BATCH, 64 threads. (R7 verbatim)
// ---------------------------------------------------------------------------
__global__ __launch_bounds__(64) void gate_kernel(
    const float* __restrict__ w1_1,
    const float* __restrict__ w5,
    const float* __restrict__ b5,
    const float* __restrict__ w6,
    const float* __restrict__ b6)
{
    __shared__ float m[64], pre[16], c1[16], up[64], hid[4][64];
    __shared__ float w1s[9], w5s[72], b5s[4], w6s[36], b6s;

    const int t = threadIdx.x;
    const int b = blockIdx.x;

    if (t < 9)  w1s[t] = w1_1[t];
    if (t < 4)  b5s[t] = b5[t];
    if (t < 36) w6s[t] = w6[t];
    if (t == 0) b6s = b6[0];
    w5s[t] = (t < 64) ? w5[t] : 0.0f;
    if (t < 8) w5s[64 + t] = w5[64 + t];

    float mv = g_part[(size_t)(b * SLICES) * HW + t];
#pragma unroll
    for (int s = 1; s < SLICES; s++)
        mv = fmaxf(mv, g_part[(size_t)(b * SLICES + s) * HW + t]);
    m[t] = mv;
    __syncthreads();

    if (t < 16) {
        int wh = t >> 2, ww = t & 3;
        float w0  = m[(2 * wh) * 8 + 2 * ww];
        float w1v = m[(2 * wh) * 8 + 2 * ww + 1];
        float w2  = m[(2 * wh + 1) * 8 + 2 * ww];
        float w3  = m[(2 * wh + 1) * 8 + 2 * ww + 1];
        float wraw[4] = {w0, w1v, w2, w3};
        float wc[4];
#pragma unroll
        for (int k = 0; k < 4; k++) {
            float val = wraw[k];
            wc[k] = (!isfinite(val) || val < 0.0f) ? EPS_F : val;
        }
        unsigned gbase = (unsigned)b * 64u + (unsigned)t * 4u;
        int best = 0;
        float bestv = wc[0] + gumbel_at(gbase);
#pragma unroll
        for (int k = 1; k < 4; k++) {
            float cand = wc[k] + gumbel_at(gbase + k);
            if (cand > bestv) { bestv = cand; best = k; }
        }
        float mo2 = wc[best];
        float mo3 = fmaxf(fmaxf(w0, w1v), fmaxf(w2, w3));
        float ao4 = (w0 + w1v + w2 + w3) * 0.25f;
        pre[t] = 0.1f * mo2 + 0.6f * mo3 + 0.3f * ao4;
    }
    __syncthreads();

    if (t < 16) {
        int i = t >> 2, j = t & 3;
        float acc1 = 0.0f;
#pragma unroll
        for (int di = 0; di < 3; di++) {
            int ii = i + di - 1;
            if (ii < 0 || ii >= 4) continue;
#pragma unroll
            for (int dj = 0; dj < 3; dj++) {
                int jj = j + dj - 1;
                if (jj < 0 || jj >= 4) continue;
                acc1 += pre[ii * 4 + jj] * w1s[di * 3 + dj];
            }
        }
        c1[t] = acc1;
    }
    __syncthreads();

    {
        const int j0t[8] = {0, 0, 0, 1, 1, 2, 2, 3};
        const int j1t[8] = {0, 1, 1, 2, 2, 3, 3, 3};
        const float wt[8] = {1.0f, 0.75f, 0.25f, 0.75f, 0.25f, 0.75f, 0.25f, 1.0f};
        int y = t >> 3, xo = t & 7;
        float wy = wt[y], wx = wt[xo];
        float r0 = wx * c1[j0t[y] * 4 + j0t[xo]] + (1.0f - wx) * c1[j0t[y] * 4 + j1t[xo]];
        float r1 = wx * c1[j1t[y] * 4 + j0t[xo]] + (1.0f - wx) * c1[j1t[y] * 4 + j1t[xo]];
        up[t] = wy * r0 + (1.0f - wy) * r1;
    }
    __syncthreads();

    {
        int y = t >> 3, xo = t & 7;
#pragma unroll
        for (int oc = 0; oc < 4; oc++) {
            float acc5 = b5s[oc];
#pragma unroll
            for (int di = 0; di < 3; di++) {
                int yy = y + di - 1;
                if (yy < 0 || yy >= 8) continue;
#pragma unroll
                for (int dj = 0; dj < 3; dj++) {
                    int xx = xo + dj - 1;
                    if (xx < 0 || xx >= 8) continue;
                    int pix = yy * 8 + xx;
                    acc5 += m[pix]  * w5s[oc * 18 + 0 * 9 + di * 3 + dj];
                    acc5 += up[pix] * w5s[oc * 18 + 1 * 9 + di * 3 + dj];
                }
            }
            hid[oc][t] = fmaxf(acc5, 0.0f);
        }
    }
    __syncthreads();

    {
        int y = t >> 3, xo = t & 7;
        float acc6 = b6s;
#pragma unroll
        for (int oc = 0; oc < 4; oc++) {
#pragma unroll
            for (int di = 0; di < 3; di++) {
                int yy = y + di - 1;
                if (yy < 0 || yy >= 8) continue;
#pragma unroll
                for (int dj = 0; dj < 3; dj++) {
                    int xx = xo + dj - 1;
                    if (xx < 0 || xx >= 8) continue;
                    acc6 += hid[oc][yy * 8 + xx] * w6s[oc * 9 + di * 3 + dj];
                }
            }
        }
        g_gate[b * HW + t] = 1.0f / (1.0f + expf(-acc6));
    }
}

// ---------------------------------------------------------------------------
// K2: out = relu(x * gate). R5 shape (512 threads, MLP=8) + R7 policies
// (reverse block order, plain cached loads, __stcs stores).
// Block covers 4096 float4 = quarter batch -> batch is block-constant.
// ---------------------------------------------------------------------------
__global__ __launch_bounds__(512) void apply_gate_kernel(
    const float4* __restrict__ x4, float4* __restrict__ out4)
{
    const int blk = gridDim.x - 1 - blockIdx.x;          // reverse order
    const size_t base = (size_t)blk * 4096 + threadIdx.x;
    const int b = (int)(base >> 14);                     // batch, block-constant
    const float4 gv = ((const float4*)g_gate)[(b << 4) | (threadIdx.x & 15)];

    float4 xv[8];
#pragma unroll
    for (int k = 0; k < 8; k++)
        xv[k] = x4[base + k * 512];

#pragma unroll
    for (int k = 0; k < 8; k++) {
        float4 o;
        o.x = fmaxf(xv[k].x * gv.x, 0.0f);
        o.y = fmaxf(xv[k].y * gv.y, 0.0f);
        o.z = fmaxf(xv[k].z * gv.z, 0.0f);
        o.w = fmaxf(xv[k].w * gv.w, 0.0f);
        __stcs(&out4[base + k * 512], o);
    }
}

extern "C" void kernel_launch(void* const* d_in, const int* in_sizes, int n_in,
                              void* d_out, int out_size)
{
    const float* x    = (const float*)d_in[0];
    const float* w1_1 = (const float*)d_in[1];
    const float* w5   = (const float*)d_in[2];
    const float* b5   = (const float*)d_in[3];
    const float* w6   = (const float*)d_in[4];
    const float* b6   = (const float*)d_in[5];
    float* out = (float*)d_out;

    partial_max_kernel<<<BATCH * SLICES, 256>>>(x);
    gate_kernel<<<BATCH, 64>>>(w1_1, w5, b5, w6, b6);

    int n4 = BATCH * CHAN * HW / 4;   // 8388608
    apply_gate_kernel<<<n4 / 4096, 512>>>((const float4*)x, (float4*)out);
}